// round 3
// baseline (speedup 1.0000x reference)
#include <cuda_runtime.h>

#define HID      64
#define TSTEPS   64
#define SEQ_TILE 32
#define NTILES   300
#define NTHREADS 256
#define HP       36
#define HSZ      (64 * HP)
#define NBLOCKS  148
#define BN_TOTAL 9600

typedef unsigned long long u64;

__device__ __forceinline__ u64 ffma2(u64 a, u64 b, u64 c) {
    u64 d;
    asm("fma.rn.f32x2 %0, %1, %2, %3;" : "=l"(d) : "l"(a), "l"(b), "l"(c));
    return d;
}
__device__ __forceinline__ u64 dup2(float w) {
    unsigned int wi = __float_as_uint(w);
    u64 r;
    asm("mov.b64 %0, {%1, %1};" : "=l"(r) : "r"(wi));
    return r;
}
__device__ __forceinline__ u64 pack2(float lo, float hi) {
    u64 r;
    asm("mov.b64 %0, {%1, %2};" : "=l"(r) : "r"(__float_as_uint(lo)), "r"(__float_as_uint(hi)));
    return r;
}
__device__ __forceinline__ float2 unpack2(u64 v) {
    unsigned int lo, hi;
    asm("mov.b64 {%0, %1}, %2;" : "=r"(lo), "=r"(hi) : "l"(v));
    return make_float2(__uint_as_float(lo), __uint_as_float(hi));
}
__device__ __forceinline__ float sigf(float x) {
    return __fdividef(1.0f, 1.0f + __expf(-x));
}
__device__ __forceinline__ float tanh_fast(float x) {
    return __fdividef(2.0f, 1.0f + __expf(-2.0f * x)) - 1.0f;
}

__global__ void __launch_bounds__(NTHREADS, 1)
lstm_kernel(const float* __restrict__ x,
            const float* __restrict__ Wih0, const float* __restrict__ Whh0,
            const float* __restrict__ bih0, const float* __restrict__ bhh0,
            const float* __restrict__ Wih1, const float* __restrict__ Whh1,
            const float* __restrict__ bih1, const float* __restrict__ bhh1,
            const float* __restrict__ fc1_w, const float* __restrict__ fc1_b,
            const float* __restrict__ fc2_w, const float* __restrict__ fc2_b,
            float* __restrict__ out)
{
    extern __shared__ float sm[];
    float* sW0 = sm;                    // [64][256]  Whh0^T  (k-major, j*4+g)
    float* sW1 = sW0 + 16384;           // Wih1^T
    float* sW2 = sW1 + 16384;           // Whh1^T
    float* sH0 = sW2 + 16384;           // [2][64][HP]  ping-pong h0, [k][seq]
    float* sH1 = sH0 + 2 * HSZ;         // [64][HP]     h1 (single buffer)

    const int tid   = threadIdx.x;
    const int j     = tid & 63;
    const int oct   = tid >> 6;
    const int sbase = oct * 8;

    // One-time weight transpose: dst[k*256 + j*4 + g] = W[(g*64+j)*64 + k]
    for (int idx = tid; idx < 16384; idx += NTHREADS) {
        int k = idx >> 8;
        int r = idx & 255;
        int jj = r >> 2, g = r & 3;
        int src = (g * 64 + jj) * 64 + k;
        sW0[idx] = Whh0[src];
        sW1[idx] = Wih1[src];
        sW2[idx] = Whh1[src];
    }

    // Per-thread constants (unit j, gates i,f,g,o) as packed duplicates
    u64 wx0d[4], b0d[4], b1d[4];
#pragma unroll
    for (int g = 0; g < 4; g++) {
        int row = g * 64 + j;
        wx0d[g] = dup2(Wih0[row]);
        b0d[g]  = dup2(bih0[row] + bhh0[row]);
        b1d[g]  = dup2(bih1[row] + bhh1[row]);
    }

    for (int tile = blockIdx.x; tile < NTILES; tile += gridDim.x) {
        const int n0 = tile * SEQ_TILE;
        __syncthreads();   // previous tile's smem readers done

        // zero the t=0 read buffers
        for (int idx = tid; idx < HSZ; idx += NTHREADS) {
            sH0[idx] = 0.0f;   // buffer p=0
            sH1[idx] = 0.0f;
        }
        float c0[8], c1[8];
#pragma unroll
        for (int s = 0; s < 8; s++) { c0[s] = 0.0f; c1[s] = 0.0f; }

        const float* xb = x + (size_t)(n0 + sbase) * TSTEPS;
        __syncthreads();

        for (int t = 0; t < TSTEPS; t++) {
            const int p = t & 1;
            const float* h0r = sH0 + p * HSZ;
            float*       h0w = sH0 + (p ^ 1) * HSZ;

            // issue x loads early; consumed after the k-loop
            float xv[8];
#pragma unroll
            for (int i = 0; i < 8; i++) xv[i] = xb[i * TSTEPS + t];

            // ---------------- layer 0 ----------------
            u64 a[4][4];
#pragma unroll
            for (int g = 0; g < 4; g++)
#pragma unroll
                for (int q = 0; q < 4; q++) a[g][q] = b0d[g];

#pragma unroll 4
            for (int k = 0; k < HID; k++) {
                const float4 w = *(const float4*)&sW0[k * 256 + (j << 2)];
                const ulonglong2 hA = *(const ulonglong2*)&h0r[k * HP + sbase];
                const ulonglong2 hB = *(const ulonglong2*)&h0r[k * HP + sbase + 4];
                const u64 hp[4] = {hA.x, hA.y, hB.x, hB.y};
                const u64 wd[4] = {dup2(w.x), dup2(w.y), dup2(w.z), dup2(w.w)};
#pragma unroll
                for (int g = 0; g < 4; g++)
#pragma unroll
                    for (int q = 0; q < 4; q++)
                        a[g][q] = ffma2(wd[g], hp[q], a[g][q]);
            }
            {
                const u64 xp[4] = {pack2(xv[0], xv[1]), pack2(xv[2], xv[3]),
                                   pack2(xv[4], xv[5]), pack2(xv[6], xv[7])};
#pragma unroll
                for (int g = 0; g < 4; g++)
#pragma unroll
                    for (int q = 0; q < 4; q++)
                        a[g][q] = ffma2(wx0d[g], xp[q], a[g][q]);
            }

            float h0n[8];
#pragma unroll
            for (int q = 0; q < 4; q++) {
                float2 iv = unpack2(a[0][q]);
                float2 fv = unpack2(a[1][q]);
                float2 gv = unpack2(a[2][q]);
                float2 ov = unpack2(a[3][q]);
                float ig0 = sigf(iv.x), ig1 = sigf(iv.y);
                float fg0 = sigf(fv.x), fg1 = sigf(fv.y);
                float gg0 = tanh_fast(gv.x), gg1 = tanh_fast(gv.y);
                float og0 = sigf(ov.x), og1 = sigf(ov.y);
                c0[2*q]   = fmaf(fg0, c0[2*q],   ig0 * gg0);
                c0[2*q+1] = fmaf(fg1, c0[2*q+1], ig1 * gg1);
                h0n[2*q]   = og0 * tanh_fast(c0[2*q]);
                h0n[2*q+1] = og1 * tanh_fast(c0[2*q+1]);
            }
            *(float4*)&h0w[j * HP + sbase]     = make_float4(h0n[0], h0n[1], h0n[2], h0n[3]);
            *(float4*)&h0w[j * HP + sbase + 4] = make_float4(h0n[4], h0n[5], h0n[6], h0n[7]);
            __syncthreads();   // h0(new) visible for layer 1

            // ---------------- layer 1 ----------------
#pragma unroll
            for (int g = 0; g < 4; g++)
#pragma unroll
                for (int q = 0; q < 4; q++) a[g][q] = b1d[g];

#pragma unroll 2
            for (int k = 0; k < HID; k++) {
                const float4 w1 = *(const float4*)&sW1[k * 256 + (j << 2)];
                const float4 w2 = *(const float4*)&sW2[k * 256 + (j << 2)];
                const ulonglong2 pA = *(const ulonglong2*)&h0w[k * HP + sbase];
                const ulonglong2 pB = *(const ulonglong2*)&h0w[k * HP + sbase + 4];
                const ulonglong2 qA = *(const ulonglong2*)&sH1[k * HP + sbase];
                const ulonglong2 qB = *(const ulonglong2*)&sH1[k * HP + sbase + 4];
                const u64 h0p[4] = {pA.x, pA.y, pB.x, pB.y};
                const u64 h1p[4] = {qA.x, qA.y, qB.x, qB.y};
                const u64 w1d[4] = {dup2(w1.x), dup2(w1.y), dup2(w1.z), dup2(w1.w)};
                const u64 w2d[4] = {dup2(w2.x), dup2(w2.y), dup2(w2.z), dup2(w2.w)};
#pragma unroll
                for (int g = 0; g < 4; g++)
#pragma unroll
                    for (int q = 0; q < 4; q++)
                        a[g][q] = ffma2(w1d[g], h0p[q], a[g][q]);
#pragma unroll
                for (int g = 0; g < 4; g++)
#pragma unroll
                    for (int q = 0; q < 4; q++)
                        a[g][q] = ffma2(w2d[g], h1p[q], a[g][q]);
            }

            float h1n[8];
#pragma unroll
            for (int q = 0; q < 4; q++) {
                float2 iv = unpack2(a[0][q]);
                float2 fv = unpack2(a[1][q]);
                float2 gv = unpack2(a[2][q]);
                float2 ov = unpack2(a[3][q]);
                float ig0 = sigf(iv.x), ig1 = sigf(iv.y);
                float fg0 = sigf(fv.x), fg1 = sigf(fv.y);
                float gg0 = tanh_fast(gv.x), gg1 = tanh_fast(gv.y);
                float og0 = sigf(ov.x), og1 = sigf(ov.y);
                c1[2*q]   = fmaf(fg0, c1[2*q],   ig0 * gg0);
                c1[2*q+1] = fmaf(fg1, c1[2*q+1], ig1 * gg1);
                h1n[2*q]   = og0 * tanh_fast(c1[2*q]);
                h1n[2*q+1] = og1 * tanh_fast(c1[2*q+1]);
            }
            __syncthreads();   // all layer-1 reads of old sH1 done
            *(float4*)&sH1[j * HP + sbase]     = make_float4(h1n[0], h1n[1], h1n[2], h1n[3]);
            *(float4*)&sH1[j * HP + sbase + 4] = make_float4(h1n[4], h1n[5], h1n[6], h1n[7]);
        }
        __syncthreads();   // final sH1 writes visible

        // ---- hT output ----
        for (int idx = tid; idx < SEQ_TILE * HID; idx += NTHREADS) {
            int s = idx >> 6, k = idx & 63;
            out[(n0 + s) * HID + k] = sH1[k * HP + s];
        }
        // ---- FC head ----
        if (tid < SEQ_TILE) {
            const int s = tid;
            const float xl = x[(size_t)(n0 + s) * TSTEPS + (TSTEPS - 1)];
            float acc = fc2_b[0];
#pragma unroll 1
            for (int u = 0; u < 16; u++) {
                float a1 = fc1_b[u];
#pragma unroll 4
                for (int k = 0; k < HID; k++)
                    a1 = fmaf(fc1_w[u * 65 + k], sH1[k * HP + s], a1);
                a1 = fmaf(fc1_w[u * 65 + 64], xl, a1);
                a1 = fmaxf(a1, 0.0f);
                acc = fmaf(fc2_w[u], a1, acc);
            }
            out[BN_TOTAL * HID + n0 + s] = acc;
        }
    }
}

extern "C" void kernel_launch(void* const* d_in, const int* in_sizes, int n_in,
                              void* d_out, int out_size) {
    (void)in_sizes; (void)n_in; (void)out_size;
    const size_t smem = (size_t)(3 * 16384 + 3 * HSZ) * sizeof(float);
    cudaFuncSetAttribute(lstm_kernel, cudaFuncAttributeMaxDynamicSharedMemorySize, (int)smem);
    lstm_kernel<<<NBLOCKS, NTHREADS, smem>>>(
        (const float*)d_in[0],  (const float*)d_in[1],  (const float*)d_in[2],
        (const float*)d_in[3],  (const float*)d_in[4],  (const float*)d_in[5],
        (const float*)d_in[6],  (const float*)d_in[7],  (const float*)d_in[8],
        (const float*)d_in[9],  (const float*)d_in[10], (const float*)d_in[11],
        (const float*)d_in[12], (float*)d_out);
}

// round 5
// speedup vs baseline: 1.6753x; 1.6753x over previous
#include <cuda_runtime.h>
#include <cuda_bf16.h>
#include <cstdint>

#define NTHREADS 512
#define NBLOCKS  148
#define NTILES   300
#define BN       9600

typedef unsigned int u32;

// ---- smem byte offsets ----
#define WLO_STRIDE 144                 // bytes per 64-col bf16 row (padded)
#define WLO_SZ     (256 * WLO_STRIDE)  // 36864
#define OFF_WLO0   0
#define OFF_WLO1   (WLO_SZ)
#define OFF_WLO2   (2 * WLO_SZ)
#define OFF_SG     (3 * WLO_SZ)        // 110592
#define SG_STRIDE  34                  // floats
#define SG_SZ      (256 * SG_STRIDE * 4)  // 34816
#define H_STRIDE   144                 // bytes per 64-col bf16 row (padded)
#define H_SZ       (32 * H_STRIDE)     // 4608
#define OFF_H0HI   (OFF_SG + SG_SZ)    // 145408
#define OFF_H0LO   (OFF_H0HI + H_SZ)
#define OFF_H1HI   (OFF_H0LO + H_SZ)
#define OFF_H1LO   (OFF_H1HI + H_SZ)
#define SMEM_BYTES (OFF_H1LO + H_SZ)   // 163840

__device__ __forceinline__ void mma16816(float* d, const u32* a, u32 b0, u32 b1) {
    asm volatile(
        "mma.sync.aligned.m16n8k16.row.col.f32.bf16.bf16.f32 "
        "{%0,%1,%2,%3}, {%4,%5,%6,%7}, {%8,%9}, {%0,%1,%2,%3};"
        : "+f"(d[0]), "+f"(d[1]), "+f"(d[2]), "+f"(d[3])
        : "r"(a[0]), "r"(a[1]), "r"(a[2]), "r"(a[3]), "r"(b0), "r"(b1));
}
__device__ __forceinline__ u32 cvt2bf(float f0, float f1) {  // low=f0, high=f1
    __nv_bfloat162 p = __floats2bfloat162_rn(f0, f1);
    return *(u32*)&p;
}
__device__ __forceinline__ float sigf(float x)   { return __fdividef(1.0f, 1.0f + __expf(-x)); }
__device__ __forceinline__ float tanhf_(float x) { return __fdividef(2.0f, 1.0f + __expf(-2.0f * x)) - 1.0f; }

__global__ void __launch_bounds__(NTHREADS, 1)
lstm_mma(const float* __restrict__ x,
         const float* __restrict__ Wih0, const float* __restrict__ Whh0,
         const float* __restrict__ bih0, const float* __restrict__ bhh0,
         const float* __restrict__ Wih1, const float* __restrict__ Whh1,
         const float* __restrict__ bih1, const float* __restrict__ bhh1,
         const float* __restrict__ fc1_w, const float* __restrict__ fc1_b,
         const float* __restrict__ fc2_w, const float* __restrict__ fc2_b,
         float* __restrict__ out)
{
    extern __shared__ char smem[];
    float* sg = (float*)(smem + OFF_SG);

    const int tid  = threadIdx.x;
    const int wid  = tid >> 5;
    const int lane = tid & 31;
    const int g4   = lane >> 2;     // fragment group 0..7
    const int t4   = lane & 3;      // fragment thread-in-group
    const int R0   = wid * 16;      // gate-row strip base
    const int j    = tid & 63;      // hidden unit (epilogue)
    const int sbase = (tid >> 6) * 4;

    // ---- W-hi fragments in registers (3 matrices x 4 ktiles x 4 regs) ----
    u32 aH0[16], aH1[16], aH2[16];
    {
        const int r0 = (R0 + g4) * 64, r1 = (R0 + g4 + 8) * 64;
#pragma unroll
        for (int kt = 0; kt < 4; kt++) {
            const int k0 = kt * 16 + 2 * t4;
            aH0[kt*4+0] = cvt2bf(Whh0[r0+k0], Whh0[r0+k0+1]);
            aH0[kt*4+1] = cvt2bf(Whh0[r1+k0], Whh0[r1+k0+1]);
            aH0[kt*4+2] = cvt2bf(Whh0[r0+k0+8], Whh0[r0+k0+9]);
            aH0[kt*4+3] = cvt2bf(Whh0[r1+k0+8], Whh0[r1+k0+9]);
            aH1[kt*4+0] = cvt2bf(Wih1[r0+k0], Wih1[r0+k0+1]);
            aH1[kt*4+1] = cvt2bf(Wih1[r1+k0], Wih1[r1+k0+1]);
            aH1[kt*4+2] = cvt2bf(Wih1[r0+k0+8], Wih1[r0+k0+9]);
            aH1[kt*4+3] = cvt2bf(Wih1[r1+k0+8], Wih1[r1+k0+9]);
            aH2[kt*4+0] = cvt2bf(Whh1[r0+k0], Whh1[r0+k0+1]);
            aH2[kt*4+1] = cvt2bf(Whh1[r1+k0], Whh1[r1+k0+1]);
            aH2[kt*4+2] = cvt2bf(Whh1[r0+k0+8], Whh1[r0+k0+9]);
            aH2[kt*4+3] = cvt2bf(Whh1[r1+k0+8], Whh1[r1+k0+9]);
        }
    }
    // ---- W-lo into smem ----
    {
        const float* Ws[3] = { Whh0, Wih1, Whh1 };
#pragma unroll 1
        for (int m = 0; m < 3; m++) {
            const float* W = Ws[m];
            char* base = smem + m * WLO_SZ;
            for (int idx = tid; idx < 16384; idx += NTHREADS) {
                int r = idx >> 6, k = idx & 63;
                float w = W[idx];
                __nv_bfloat16 hb = __float2bfloat16(w);
                float lo = w - __bfloat162float(hb);
                *(__nv_bfloat16*)(base + r * WLO_STRIDE + k * 2) = __float2bfloat16(lo);
            }
        }
    }
    // epilogue constants
    float wxg[4], b0g[4], b1g[4];
#pragma unroll
    for (int g = 0; g < 4; g++) {
        int row = g * 64 + j;
        wxg[g] = Wih0[row];
        b0g[g] = bih0[row] + bhh0[row];
        b1g[g] = bih1[row] + bhh1[row];
    }
    __syncthreads();

    for (int tile = blockIdx.x; tile < NTILES; tile += gridDim.x) {
        const int n0 = tile * 32;
        __syncthreads();   // previous tile's smem readers done
        u32* hz = (u32*)(smem + OFF_H0HI);
        for (int i = tid; i < 4 * H_SZ / 4; i += NTHREADS) hz[i] = 0u;
        float c0[4], c1[4], h1v[4];
#pragma unroll
        for (int s = 0; s < 4; s++) { c0[s] = 0.0f; c1[s] = 0.0f; h1v[s] = 0.0f; }
        __syncthreads();

        for (int tt = 0; tt < 64; tt++) {
            float xv[4];
#pragma unroll
            for (int s = 0; s < 4; s++) xv[s] = __ldg(x + (size_t)(n0 + sbase + s) * 64 + tt);

            // ============ layer 0 MMA: gates0 = Whh0 @ h0 ============
            {
                float d[4][4];
#pragma unroll
                for (int nt = 0; nt < 4; nt++)
#pragma unroll
                    for (int i = 0; i < 4; i++) d[nt][i] = 0.0f;
#pragma unroll
                for (int kt = 0; kt < 4; kt++) {
                    const u32 ro = (u32)((R0 + g4) * WLO_STRIDE + kt * 32 + t4 * 4);
                    u32 l[4];
                    l[0] = *(const u32*)(smem + OFF_WLO0 + ro);
                    l[1] = *(const u32*)(smem + OFF_WLO0 + ro + 8 * WLO_STRIDE);
                    l[2] = *(const u32*)(smem + OFF_WLO0 + ro + 16);
                    l[3] = *(const u32*)(smem + OFF_WLO0 + ro + 8 * WLO_STRIDE + 16);
#pragma unroll
                    for (int nt = 0; nt < 4; nt++) {
                        const u32 bo = (u32)((nt * 8 + g4) * H_STRIDE + kt * 32 + t4 * 4);
                        u32 b0h = *(const u32*)(smem + OFF_H0HI + bo);
                        u32 b1h = *(const u32*)(smem + OFF_H0HI + bo + 16);
                        u32 b0l = *(const u32*)(smem + OFF_H0LO + bo);
                        u32 b1l = *(const u32*)(smem + OFF_H0LO + bo + 16);
                        mma16816(d[nt], &aH0[kt*4], b0h, b1h);
                        mma16816(d[nt], &aH0[kt*4], b0l, b1l);
                        mma16816(d[nt], l, b0h, b1h);
                    }
                }
#pragma unroll
                for (int nt = 0; nt < 4; nt++) {
                    *(float2*)&sg[(R0 + g4) * SG_STRIDE + nt * 8 + 2 * t4]     = make_float2(d[nt][0], d[nt][1]);
                    *(float2*)&sg[(R0 + g4 + 8) * SG_STRIDE + nt * 8 + 2 * t4] = make_float2(d[nt][2], d[nt][3]);
                }
            }
            __syncthreads();

            // ============ layer 0 epilogue ============
#pragma unroll
            for (int s = 0; s < 4; s++) {
                float pi = sg[(0 * 64 + j) * SG_STRIDE + sbase + s] + b0g[0] + wxg[0] * xv[s];
                float pf = sg[(1 * 64 + j) * SG_STRIDE + sbase + s] + b0g[1] + wxg[1] * xv[s];
                float pg = sg[(2 * 64 + j) * SG_STRIDE + sbase + s] + b0g[2] + wxg[2] * xv[s];
                float po = sg[(3 * 64 + j) * SG_STRIDE + sbase + s] + b0g[3] + wxg[3] * xv[s];
                float I = sigf(pi), F = sigf(pf), G = tanhf_(pg), O = sigf(po);
                c0[s] = fmaf(F, c0[s], I * G);
                float h0 = O * tanhf_(c0[s]);
                __nv_bfloat16 hb = __float2bfloat16(h0);
                __nv_bfloat16 lb = __float2bfloat16(h0 - __bfloat162float(hb));
                u32 ho = (u32)((sbase + s) * H_STRIDE + j * 2);
                *(__nv_bfloat16*)(smem + OFF_H0HI + ho) = hb;
                *(__nv_bfloat16*)(smem + OFF_H0LO + ho) = lb;
            }
            __syncthreads();

            // ============ layer 1 MMA: gates1 = Wih1 @ h0new + Whh1 @ h1 ============
            {
                float d[4][4];
#pragma unroll
                for (int nt = 0; nt < 4; nt++)
#pragma unroll
                    for (int i = 0; i < 4; i++) d[nt][i] = 0.0f;
#pragma unroll
                for (int kt = 0; kt < 4; kt++) {
                    const u32 ro = (u32)((R0 + g4) * WLO_STRIDE + kt * 32 + t4 * 4);
                    u32 l1[4], l2[4];
                    l1[0] = *(const u32*)(smem + OFF_WLO1 + ro);
                    l1[1] = *(const u32*)(smem + OFF_WLO1 + ro + 8 * WLO_STRIDE);
                    l1[2] = *(const u32*)(smem + OFF_WLO1 + ro + 16);
                    l1[3] = *(const u32*)(smem + OFF_WLO1 + ro + 8 * WLO_STRIDE + 16);
                    l2[0] = *(const u32*)(smem + OFF_WLO2 + ro);
                    l2[1] = *(const u32*)(smem + OFF_WLO2 + ro + 8 * WLO_STRIDE);
                    l2[2] = *(const u32*)(smem + OFF_WLO2 + ro + 16);
                    l2[3] = *(const u32*)(smem + OFF_WLO2 + ro + 8 * WLO_STRIDE + 16);
#pragma unroll
                    for (int nt = 0; nt < 4; nt++) {
                        const u32 bo = (u32)((nt * 8 + g4) * H_STRIDE + kt * 32 + t4 * 4);
                        u32 p0h = *(const u32*)(smem + OFF_H0HI + bo);
                        u32 p1h = *(const u32*)(smem + OFF_H0HI + bo + 16);
                        u32 p0l = *(const u32*)(smem + OFF_H0LO + bo);
                        u32 p1l = *(const u32*)(smem + OFF_H0LO + bo + 16);
                        u32 q0h = *(const u32*)(smem + OFF_H1HI + bo);
                        u32 q1h = *(const u32*)(smem + OFF_H1HI + bo + 16);
                        u32 q0l = *(const u32*)(smem + OFF_H1LO + bo);
                        u32 q1l = *(const u32*)(smem + OFF_H1LO + bo + 16);
                        mma16816(d[nt], &aH1[kt*4], p0h, p1h);
                        mma16816(d[nt], &aH1[kt*4], p0l, p1l);
                        mma16816(d[nt], l1, p0h, p1h);
                        mma16816(d[nt], &aH2[kt*4], q0h, q1h);
                        mma16816(d[nt], &aH2[kt*4], q0l, q1l);
                        mma16816(d[nt], l2, q0h, q1h);
                    }
                }
#pragma unroll
                for (int nt = 0; nt < 4; nt++) {
                    *(float2*)&sg[(R0 + g4) * SG_STRIDE + nt * 8 + 2 * t4]     = make_float2(d[nt][0], d[nt][1]);
                    *(float2*)&sg[(R0 + g4 + 8) * SG_STRIDE + nt * 8 + 2 * t4] = make_float2(d[nt][2], d[nt][3]);
                }
            }
            __syncthreads();

            // ============ layer 1 epilogue ============
#pragma unroll
            for (int s = 0; s < 4; s++) {
                float pi = sg[(0 * 64 + j) * SG_STRIDE + sbase + s] + b1g[0];
                float pf = sg[(1 * 64 + j) * SG_STRIDE + sbase + s] + b1g[1];
                float pg = sg[(2 * 64 + j) * SG_STRIDE + sbase + s] + b1g[2];
                float po = sg[(3 * 64 + j) * SG_STRIDE + sbase + s] + b1g[3];
                float I = sigf(pi), F = sigf(pf), G = tanhf_(pg), O = sigf(po);
                c1[s] = fmaf(F, c1[s], I * G);
                float h1 = O * tanhf_(c1[s]);
                h1v[s] = h1;
                __nv_bfloat16 hb = __float2bfloat16(h1);
                __nv_bfloat16 lb = __float2bfloat16(h1 - __bfloat162float(hb));
                u32 ho = (u32)((sbase + s) * H_STRIDE + j * 2);
                *(__nv_bfloat16*)(smem + OFF_H1HI + ho) = hb;
                *(__nv_bfloat16*)(smem + OFF_H1LO + ho) = lb;
            }
            __syncthreads();
        }

        // ---- outputs ----
#pragma unroll
        for (int s = 0; s < 4; s++) out[(size_t)(n0 + sbase + s) * 64 + j] = h1v[s];
#pragma unroll
        for (int s = 0; s < 4; s++) sg[j * SG_STRIDE + sbase + s] = h1v[s];
        __syncthreads();
        if (tid < 32) {
            const int s = tid;
            const float xl = x[(size_t)(n0 + s) * 64 + 63];
            float acc = fc2_b[0];
#pragma unroll 1
            for (int u = 0; u < 16; u++) {
                float a1 = fc1_b[u];
#pragma unroll 4
                for (int k = 0; k < 64; k++)
                    a1 = fmaf(fc1_w[u * 65 + k], sg[k * SG_STRIDE + s], a1);
                a1 = fmaf(fc1_w[u * 65 + 64], xl, a1);
                acc = fmaf(fc2_w[u], fmaxf(a1, 0.0f), acc);
            }
            out[(size_t)BN * 64 + n0 + s] = acc;
        }
    }
}

extern "C" void kernel_launch(void* const* d_in, const int* in_sizes, int n_in,
                              void* d_out, int out_size) {
    (void)in_sizes; (void)n_in; (void)out_size;
    cudaFuncSetAttribute(lstm_mma, cudaFuncAttributeMaxDynamicSharedMemorySize, SMEM_BYTES);
    lstm_mma<<<NBLOCKS, NTHREADS, SMEM_BYTES>>>(
        (const float*)d_in[0],  (const float*)d_in[1],  (const float*)d_in[2],
        (const float*)d_in[3],  (const float*)d_in[4],  (const float*)d_in[5],
        (const float*)d_in[6],  (const float*)d_in[7],  (const float*)d_in[8],
        (const float*)d_in[9],  (const float*)d_in[10], (const float*)d_in[11],
        (const float*)d_in[12], (float*)d_out);
}

// round 6
// speedup vs baseline: 2.6373x; 1.5742x over previous
#include <cuda_runtime.h>
#include <cuda_bf16.h>
#include <cstdint>

#define NTHREADS 512
#define NBLOCKS  148
#define SEQ_TILE 24
#define NTILES   400
#define BN       9600

typedef unsigned int u32;

// ---- smem layout ----
#define WLO_STRIDE 144
#define WLO_SZ     (256 * WLO_STRIDE)       // 36864
#define OFF_WLO0   0
#define OFF_WLO1   (WLO_SZ)
#define OFF_WLO2   (2 * WLO_SZ)
#define OFF_SG     (3 * WLO_SZ)             // 110592
#define SG_STRIDE  36
#define SG_SZ      (256 * SG_STRIDE * 4)    // 36864
#define H_STRIDE   144
#define H_SZ       (SEQ_TILE * H_STRIDE)    // 3456
#define OFF_H0HI   (OFF_SG + SG_SZ)         // 147456
#define OFF_H0LO   (OFF_H0HI + H_SZ)
#define OFF_H1HI   (OFF_H0LO + H_SZ)
#define OFF_H1LO   (OFF_H1HI + H_SZ)
#define SMEM_BYTES (OFF_H1LO + H_SZ)        // 161280

__device__ __forceinline__ void mma16816(float* d, const u32* a, u32 b0, u32 b1) {
    asm volatile(
        "mma.sync.aligned.m16n8k16.row.col.f32.bf16.bf16.f32 "
        "{%0,%1,%2,%3}, {%4,%5,%6,%7}, {%8,%9}, {%0,%1,%2,%3};"
        : "+f"(d[0]), "+f"(d[1]), "+f"(d[2]), "+f"(d[3])
        : "r"(a[0]), "r"(a[1]), "r"(a[2]), "r"(a[3]), "r"(b0), "r"(b1));
}
__device__ __forceinline__ u32 cvt2bf(float f0, float f1) {
    __nv_bfloat162 p = __floats2bfloat162_rn(f0, f1);
    return *(u32*)&p;
}
__device__ __forceinline__ float tanha(float x) {
    float r;
    asm("tanh.approx.f32 %0, %1;" : "=f"(r) : "f"(x));
    return r;
}
__device__ __forceinline__ float siga(float x) {      // sigmoid(x) = 0.5 + 0.5*tanh(x/2)
    return fmaf(0.5f, tanha(0.5f * x), 0.5f);
}

__global__ void __launch_bounds__(NTHREADS, 1)
lstm_mma(const float* __restrict__ x,
         const float* __restrict__ Wih0, const float* __restrict__ Whh0,
         const float* __restrict__ bih0, const float* __restrict__ bhh0,
         const float* __restrict__ Wih1, const float* __restrict__ Whh1,
         const float* __restrict__ bih1, const float* __restrict__ bhh1,
         const float* __restrict__ fc1_w, const float* __restrict__ fc1_b,
         const float* __restrict__ fc2_w, const float* __restrict__ fc2_b,
         float* __restrict__ out)
{
    extern __shared__ char smem[];
    float* sg = (float*)(smem + OFF_SG);

    const int tid  = threadIdx.x;
    const int wid  = tid >> 5;
    const int lane = tid & 31;
    const int g4   = lane >> 2;
    const int t4   = lane & 3;
    const int R0   = wid * 16;
    const int j    = tid & 63;
    const int sbase = (tid >> 6) * 4;
    const bool act  = sbase < SEQ_TILE;     // epilogue-active thread

    // ---- W-hi fragments in registers ----
    u32 aH0[16], aH1[16], aH2[16];
    {
        const int r0 = (R0 + g4) * 64, r1 = (R0 + g4 + 8) * 64;
#pragma unroll
        for (int kt = 0; kt < 4; kt++) {
            const int k0 = kt * 16 + 2 * t4;
            aH0[kt*4+0] = cvt2bf(Whh0[r0+k0], Whh0[r0+k0+1]);
            aH0[kt*4+1] = cvt2bf(Whh0[r1+k0], Whh0[r1+k0+1]);
            aH0[kt*4+2] = cvt2bf(Whh0[r0+k0+8], Whh0[r0+k0+9]);
            aH0[kt*4+3] = cvt2bf(Whh0[r1+k0+8], Whh0[r1+k0+9]);
            aH1[kt*4+0] = cvt2bf(Wih1[r0+k0], Wih1[r0+k0+1]);
            aH1[kt*4+1] = cvt2bf(Wih1[r1+k0], Wih1[r1+k0+1]);
            aH1[kt*4+2] = cvt2bf(Wih1[r0+k0+8], Wih1[r0+k0+9]);
            aH1[kt*4+3] = cvt2bf(Wih1[r1+k0+8], Wih1[r1+k0+9]);
            aH2[kt*4+0] = cvt2bf(Whh1[r0+k0], Whh1[r0+k0+1]);
            aH2[kt*4+1] = cvt2bf(Whh1[r1+k0], Whh1[r1+k0+1]);
            aH2[kt*4+2] = cvt2bf(Whh1[r0+k0+8], Whh1[r0+k0+9]);
            aH2[kt*4+3] = cvt2bf(Whh1[r1+k0+8], Whh1[r1+k0+9]);
        }
    }
    // ---- W-lo into smem ----
    {
        const float* Ws[3] = { Whh0, Wih1, Whh1 };
#pragma unroll 1
        for (int m = 0; m < 3; m++) {
            const float* W = Ws[m];
            char* base = smem + m * WLO_SZ;
            for (int idx = tid; idx < 16384; idx += NTHREADS) {
                int r = idx >> 6, k = idx & 63;
                float w = W[idx];
                __nv_bfloat16 hb = __float2bfloat16(w);
                float lo = w - __bfloat162float(hb);
                *(__nv_bfloat16*)(base + r * WLO_STRIDE + k * 2) = __float2bfloat16(lo);
            }
        }
    }
    float wxg[4], b0g[4], b1g[4];
#pragma unroll
    for (int g = 0; g < 4; g++) {
        int row = g * 64 + j;
        wxg[g] = Wih0[row];
        b0g[g] = bih0[row] + bhh0[row];
        b1g[g] = bih1[row] + bhh1[row];
    }
    __syncthreads();

    for (int tile = blockIdx.x; tile < NTILES; tile += gridDim.x) {
        const int n0 = tile * SEQ_TILE;
        __syncthreads();
        u32* hz = (u32*)(smem + OFF_H0HI);
        for (int i = tid; i < 4 * H_SZ / 4; i += NTHREADS) hz[i] = 0u;
        float c0[4], c1[4], h1v[4];
#pragma unroll
        for (int s = 0; s < 4; s++) { c0[s] = 0.0f; c1[s] = 0.0f; h1v[s] = 0.0f; }
        __syncthreads();

        for (int tt = 0; tt < 64; tt++) {
            float xv[4];
            if (act) {
#pragma unroll
                for (int s = 0; s < 4; s++) xv[s] = __ldg(x + (size_t)(n0 + sbase + s) * 64 + tt);
            }

            // ===== layer 0: gates0 = Whh0 @ h0 (3-pass bf16 split) =====
            {
                float d[3][4];
#pragma unroll
                for (int nt = 0; nt < 3; nt++)
#pragma unroll
                    for (int i = 0; i < 4; i++) d[nt][i] = 0.0f;
#pragma unroll
                for (int kt = 0; kt < 4; kt++) {
                    const u32 ro = (u32)((R0 + g4) * WLO_STRIDE + kt * 32 + t4 * 4);
                    u32 l[4];
                    l[0] = *(const u32*)(smem + OFF_WLO0 + ro);
                    l[1] = *(const u32*)(smem + OFF_WLO0 + ro + 8 * WLO_STRIDE);
                    l[2] = *(const u32*)(smem + OFF_WLO0 + ro + 16);
                    l[3] = *(const u32*)(smem + OFF_WLO0 + ro + 8 * WLO_STRIDE + 16);
#pragma unroll
                    for (int nt = 0; nt < 3; nt++) {
                        const u32 bo = (u32)((nt * 8 + g4) * H_STRIDE + kt * 32 + t4 * 4);
                        u32 b0h = *(const u32*)(smem + OFF_H0HI + bo);
                        u32 b1h = *(const u32*)(smem + OFF_H0HI + bo + 16);
                        u32 b0l = *(const u32*)(smem + OFF_H0LO + bo);
                        u32 b1l = *(const u32*)(smem + OFF_H0LO + bo + 16);
                        mma16816(d[nt], &aH0[kt*4], b0h, b1h);
                        mma16816(d[nt], &aH0[kt*4], b0l, b1l);
                        mma16816(d[nt], l, b0h, b1h);
                    }
                }
#pragma unroll
                for (int nt = 0; nt < 3; nt++) {
                    *(float2*)&sg[(R0 + g4) * SG_STRIDE + nt * 8 + 2 * t4]     = make_float2(d[nt][0], d[nt][1]);
                    *(float2*)&sg[(R0 + g4 + 8) * SG_STRIDE + nt * 8 + 2 * t4] = make_float2(d[nt][2], d[nt][3]);
                }
            }
            __syncthreads();

            // ===== layer 0 epilogue =====
            if (act) {
                float4 pi = *(const float4*)&sg[(0 * 64 + j) * SG_STRIDE + sbase];
                float4 pf = *(const float4*)&sg[(1 * 64 + j) * SG_STRIDE + sbase];
                float4 pg = *(const float4*)&sg[(2 * 64 + j) * SG_STRIDE + sbase];
                float4 po = *(const float4*)&sg[(3 * 64 + j) * SG_STRIDE + sbase];
                float pis[4] = {pi.x, pi.y, pi.z, pi.w};
                float pfs[4] = {pf.x, pf.y, pf.z, pf.w};
                float pgs[4] = {pg.x, pg.y, pg.z, pg.w};
                float pos[4] = {po.x, po.y, po.z, po.w};
#pragma unroll
                for (int s = 0; s < 4; s++) {
                    float I = siga(fmaf(wxg[0], xv[s], pis[s] + b0g[0]));
                    float F = siga(fmaf(wxg[1], xv[s], pfs[s] + b0g[1]));
                    float G = tanha(fmaf(wxg[2], xv[s], pgs[s] + b0g[2]));
                    float O = siga(fmaf(wxg[3], xv[s], pos[s] + b0g[3]));
                    c0[s] = fmaf(F, c0[s], I * G);
                    float h0 = O * tanha(c0[s]);
                    __nv_bfloat16 hb = __float2bfloat16(h0);
                    __nv_bfloat16 lb = __float2bfloat16(h0 - __bfloat162float(hb));
                    u32 ho = (u32)((sbase + s) * H_STRIDE + j * 2);
                    *(__nv_bfloat16*)(smem + OFF_H0HI + ho) = hb;
                    *(__nv_bfloat16*)(smem + OFF_H0LO + ho) = lb;
                }
            }
            __syncthreads();

            // ===== layer 1: gates1 = Wih1 @ h0new + Whh1 @ h1 =====
            {
                float d[3][4];
#pragma unroll
                for (int nt = 0; nt < 3; nt++)
#pragma unroll
                    for (int i = 0; i < 4; i++) d[nt][i] = 0.0f;
#pragma unroll
                for (int kt = 0; kt < 4; kt++) {
                    const u32 ro = (u32)((R0 + g4) * WLO_STRIDE + kt * 32 + t4 * 4);
                    u32 l1[4], l2[4];
                    l1[0] = *(const u32*)(smem + OFF_WLO1 + ro);
                    l1[1] = *(const u32*)(smem + OFF_WLO1 + ro + 8 * WLO_STRIDE);
                    l1[2] = *(const u32*)(smem + OFF_WLO1 + ro + 16);
                    l1[3] = *(const u32*)(smem + OFF_WLO1 + ro + 8 * WLO_STRIDE + 16);
                    l2[0] = *(const u32*)(smem + OFF_WLO2 + ro);
                    l2[1] = *(const u32*)(smem + OFF_WLO2 + ro + 8 * WLO_STRIDE);
                    l2[2] = *(const u32*)(smem + OFF_WLO2 + ro + 16);
                    l2[3] = *(const u32*)(smem + OFF_WLO2 + ro + 8 * WLO_STRIDE + 16);
#pragma unroll
                    for (int nt = 0; nt < 3; nt++) {
                        const u32 bo = (u32)((nt * 8 + g4) * H_STRIDE + kt * 32 + t4 * 4);
                        u32 p0h = *(const u32*)(smem + OFF_H0HI + bo);
                        u32 p1h = *(const u32*)(smem + OFF_H0HI + bo + 16);
                        u32 p0l = *(const u32*)(smem + OFF_H0LO + bo);
                        u32 p1l = *(const u32*)(smem + OFF_H0LO + bo + 16);
                        u32 q0h = *(const u32*)(smem + OFF_H1HI + bo);
                        u32 q1h = *(const u32*)(smem + OFF_H1HI + bo + 16);
                        u32 q0l = *(const u32*)(smem + OFF_H1LO + bo);
                        u32 q1l = *(const u32*)(smem + OFF_H1LO + bo + 16);
                        mma16816(d[nt], &aH1[kt*4], p0h, p1h);
                        mma16816(d[nt], &aH1[kt*4], p0l, p1l);
                        mma16816(d[nt], l1, p0h, p1h);
                        mma16816(d[nt], &aH2[kt*4], q0h, q1h);
                        mma16816(d[nt], &aH2[kt*4], q0l, q1l);
                        mma16816(d[nt], l2, q0h, q1h);
                    }
                }
#pragma unroll
                for (int nt = 0; nt < 3; nt++) {
                    *(float2*)&sg[(R0 + g4) * SG_STRIDE + nt * 8 + 2 * t4]     = make_float2(d[nt][0], d[nt][1]);
                    *(float2*)&sg[(R0 + g4 + 8) * SG_STRIDE + nt * 8 + 2 * t4] = make_float2(d[nt][2], d[nt][3]);
                }
            }
            __syncthreads();

            // ===== layer 1 epilogue =====
            if (act) {
                float4 pi = *(const float4*)&sg[(0 * 64 + j) * SG_STRIDE + sbase];
                float4 pf = *(const float4*)&sg[(1 * 64 + j) * SG_STRIDE + sbase];
                float4 pg = *(const float4*)&sg[(2 * 64 + j) * SG_STRIDE + sbase];
                float4 po = *(const float4*)&sg[(3 * 64 + j) * SG_STRIDE + sbase];
                float pis[4] = {pi.x, pi.y, pi.z, pi.w};
                float pfs[4] = {pf.x, pf.y, pf.z, pf.w};
                float pgs[4] = {pg.x, pg.y, pg.z, pg.w};
                float pos[4] = {po.x, po.y, po.z, po.w};
#pragma unroll
                for (int s = 0; s < 4; s++) {
                    float I = siga(pis[s] + b1g[0]);
                    float F = siga(pfs[s] + b1g[1]);
                    float G = tanha(pgs[s] + b1g[2]);
                    float O = siga(pos[s] + b1g[3]);
                    c1[s] = fmaf(F, c1[s], I * G);
                    float h1 = O * tanha(c1[s]);
                    h1v[s] = h1;
                    __nv_bfloat16 hb = __float2bfloat16(h1);
                    __nv_bfloat16 lb = __float2bfloat16(h1 - __bfloat162float(hb));
                    u32 ho = (u32)((sbase + s) * H_STRIDE + j * 2);
                    *(__nv_bfloat16*)(smem + OFF_H1HI + ho) = hb;
                    *(__nv_bfloat16*)(smem + OFF_H1LO + ho) = lb;
                }
            }
            __syncthreads();
        }

        // ---- outputs ----
        if (act) {
#pragma unroll
            for (int s = 0; s < 4; s++) out[(size_t)(n0 + sbase + s) * 64 + j] = h1v[s];
#pragma unroll
            for (int s = 0; s < 4; s++) sg[j * SG_STRIDE + sbase + s] = h1v[s];
        }
        __syncthreads();
        if (tid < SEQ_TILE) {
            const int s = tid;
            const float xl = x[(size_t)(n0 + s) * 64 + 63];
            float acc = fc2_b[0];
#pragma unroll 1
            for (int u = 0; u < 16; u++) {
                float a1 = fc1_b[u];
#pragma unroll 4
                for (int k = 0; k < 64; k++)
                    a1 = fmaf(fc1_w[u * 65 + k], sg[k * SG_STRIDE + s], a1);
                a1 = fmaf(fc1_w[u * 65 + 64], xl, a1);
                acc = fmaf(fc2_w[u], fmaxf(a1, 0.0f), acc);
            }
            out[(size_t)BN * 64 + n0 + s] = acc;
        }
    }
}

extern "C" void kernel_launch(void* const* d_in, const int* in_sizes, int n_in,
                              void* d_out, int out_size) {
    (void)in_sizes; (void)n_in; (void)out_size;
    cudaFuncSetAttribute(lstm_mma, cudaFuncAttributeMaxDynamicSharedMemorySize, SMEM_BYTES);
    lstm_mma<<<NBLOCKS, NTHREADS, SMEM_BYTES>>>(
        (const float*)d_in[0],  (const float*)d_in[1],  (const float*)d_in[2],
        (const float*)d_in[3],  (const float*)d_in[4],  (const float*)d_in[5],
        (const float*)d_in[6],  (const float*)d_in[7],  (const float*)d_in[8],
        (const float*)d_in[9],  (const float*)d_in[10], (const float*)d_in[11],
        (const float*)d_in[12], (float*)d_out);
}

// round 7
// speedup vs baseline: 4.7322x; 1.7944x over previous
#include <cuda_runtime.h>
#include <cuda_fp16.h>
#include <cstdint>

#define NTHREADS 256
#define NBLOCKS  148
#define BN       9600
#define SEQ_CAP  72
#define NT       9

typedef unsigned int u32;

#define H_STRIDE 144
#define HB_SZ    (SEQ_CAP * H_STRIDE)          // 10368
#define OFF_X    (8 * HB_SZ)                   // 82944
#define SMEM_BYTES (OFF_X + SEQ_CAP * 65 * 4)  // 101664
// h buffer: (layer l, ping p, part: 0=hi 1=lo)
#define HOFF(l, p, part) (((l) * 4 + (p) * 2 + (part)) * HB_SZ)

__device__ __forceinline__ void mmaf16(float* d, const u32* a, u32 b0, u32 b1) {
    asm volatile(
        "mma.sync.aligned.m16n8k16.row.col.f32.f16.f16.f32 "
        "{%0,%1,%2,%3}, {%4,%5,%6,%7}, {%8,%9}, {%0,%1,%2,%3};"
        : "+f"(d[0]), "+f"(d[1]), "+f"(d[2]), "+f"(d[3])
        : "r"(a[0]), "r"(a[1]), "r"(a[2]), "r"(a[3]), "r"(b0), "r"(b1));
}
__device__ __forceinline__ u32 h2u(float f0, float f1) {
    __half2 h = __floats2half2_rn(f0, f1);
    return *(u32*)&h;
}
__device__ __forceinline__ float tanha(float x) {
    float r;
    asm("tanh.approx.f32 %0, %1;" : "=f"(r) : "f"(x));
    return r;
}
__device__ __forceinline__ float siga(float x) { return fmaf(0.5f, tanha(0.5f * x), 0.5f); }

__device__ __forceinline__ void wr_h(char* base_hi, char* base_lo, int s, int u, float h) {
    __half hh = __float2half_rn(h);
    float lo = h - __half2float(hh);
    u32 off = (u32)(s * H_STRIDE + u * 2);
    *(__half*)(base_hi + off) = hh;
    *(__half*)(base_lo + off) = __float2half_rn(lo);
}

__global__ void __launch_bounds__(NTHREADS, 1)
lstm_mma(const float* __restrict__ x,
         const float* __restrict__ Wih0, const float* __restrict__ Whh0,
         const float* __restrict__ bih0, const float* __restrict__ bhh0,
         const float* __restrict__ Wih1, const float* __restrict__ Whh1,
         const float* __restrict__ bih1, const float* __restrict__ bhh1,
         const float* __restrict__ fc1_w, const float* __restrict__ fc1_b,
         const float* __restrict__ fc2_w, const float* __restrict__ fc2_b,
         float* __restrict__ out)
{
    extern __shared__ char smem[];
    float* sx = (float*)(smem + OFF_X);

    const int tid  = threadIdx.x;
    const int wid  = tid >> 5;
    const int lane = tid & 31;
    const int g4   = lane >> 2;
    const int t4   = lane & 3;
    const int u    = wid * 8 + g4;          // hidden unit owned by this thread
    const int b    = blockIdx.x;
    const int cnt  = 64 + (b < 128 ? 1 : 0);
    const int start = b * 64 + (b < 128 ? b : 128);

    // ---- W-hi fp16 A-fragments in registers (permuted rows: tile T -> gates 2T,2T+1; unit u) ----
    u32 aW0[32], aW1[32], aW2[32];
#pragma unroll
    for (int kt = 0; kt < 4; kt++)
#pragma unroll
        for (int T = 0; T < 2; T++) {
            const int r0 = ((2 * T) * 64 + u) * 64;      // gate 2T row
            const int r1 = ((2 * T + 1) * 64 + u) * 64;  // gate 2T+1 row
            const int k0 = kt * 16 + 2 * t4;
            const int i = kt * 8 + T * 4;
            aW0[i+0] = h2u(Whh0[r0+k0],   Whh0[r0+k0+1]);
            aW0[i+1] = h2u(Whh0[r1+k0],   Whh0[r1+k0+1]);
            aW0[i+2] = h2u(Whh0[r0+k0+8], Whh0[r0+k0+9]);
            aW0[i+3] = h2u(Whh0[r1+k0+8], Whh0[r1+k0+9]);
            aW1[i+0] = h2u(Wih1[r0+k0],   Wih1[r0+k0+1]);
            aW1[i+1] = h2u(Wih1[r1+k0],   Wih1[r1+k0+1]);
            aW1[i+2] = h2u(Wih1[r0+k0+8], Wih1[r0+k0+9]);
            aW1[i+3] = h2u(Wih1[r1+k0+8], Wih1[r1+k0+9]);
            aW2[i+0] = h2u(Whh1[r0+k0],   Whh1[r0+k0+1]);
            aW2[i+1] = h2u(Whh1[r1+k0],   Whh1[r1+k0+1]);
            aW2[i+2] = h2u(Whh1[r0+k0+8], Whh1[r0+k0+9]);
            aW2[i+3] = h2u(Whh1[r1+k0+8], Whh1[r1+k0+9]);
        }

    float wxg[4], b0g[4], b1g[4];
#pragma unroll
    for (int g = 0; g < 4; g++) {
        int row = g * 64 + u;
        wxg[g] = Wih0[row];
        b0g[g] = bih0[row] + bhh0[row];
        b1g[g] = bih1[row] + bhh1[row];
    }

    // ---- zero h buffers; stage x ----
    for (int i = tid; i < (8 * HB_SZ) / 4; i += NTHREADS) ((u32*)smem)[i] = 0u;
    for (int i = tid; i < SEQ_CAP * 64; i += NTHREADS) {
        int s = i >> 6, t = i & 63;
        sx[s * 65 + t] = (s < cnt) ? x[(size_t)(start + s) * 64 + t] : 0.0f;
    }
    __syncthreads();

    float c0[2 * NT], c1[2 * NT];
#pragma unroll
    for (int i = 0; i < 2 * NT; i++) { c0[i] = 0.0f; c1[i] = 0.0f; }

    for (int tt = 0; tt < 64; tt++) {
        const int p = tt & 1;
        char* h0r_hi = smem + HOFF(0, p, 0);
        char* h0r_lo = smem + HOFF(0, p, 1);
        char* h0w_hi = smem + HOFF(0, p ^ 1, 0);
        char* h0w_lo = smem + HOFF(0, p ^ 1, 1);
        char* h1r_hi = smem + HOFF(1, p, 0);
        char* h1r_lo = smem + HOFF(1, p, 1);
        char* h1w_hi = smem + HOFF(1, p ^ 1, 0);
        char* h1w_lo = smem + HOFF(1, p ^ 1, 1);

        // ================= layer 0 =================
#pragma unroll
        for (int nt = 0; nt < NT; nt++) {
            float dif[4] = {0,0,0,0}, dgo[4] = {0,0,0,0};
#pragma unroll
            for (int kt = 0; kt < 4; kt++) {
                const u32 ro = (u32)((nt * 8 + g4) * H_STRIDE + kt * 32 + t4 * 4);
                u32 b0h = *(const u32*)(h0r_hi + ro);
                u32 b1h = *(const u32*)(h0r_hi + ro + 16);
                u32 b0l = *(const u32*)(h0r_lo + ro);
                u32 b1l = *(const u32*)(h0r_lo + ro + 16);
                mmaf16(dif, &aW0[kt*8+0], b0h, b1h);
                mmaf16(dif, &aW0[kt*8+0], b0l, b1l);
                mmaf16(dgo, &aW0[kt*8+4], b0h, b1h);
                mmaf16(dgo, &aW0[kt*8+4], b0l, b1l);
            }
            const int s0 = nt * 8 + 2 * t4;
            const float x0 = sx[s0 * 65 + tt];
            const float x1 = sx[s0 * 65 + 65 + tt];
            const int e = nt * 2;
            {
                float I = siga(fmaf(wxg[0], x0, dif[0] + b0g[0]));
                float F = siga(fmaf(wxg[1], x0, dif[2] + b0g[1]));
                float G = tanha(fmaf(wxg[2], x0, dgo[0] + b0g[2]));
                float O = siga(fmaf(wxg[3], x0, dgo[2] + b0g[3]));
                c0[e] = fmaf(F, c0[e], I * G);
                wr_h(h0w_hi, h0w_lo, s0, u, O * tanha(c0[e]));
            }
            {
                float I = siga(fmaf(wxg[0], x1, dif[1] + b0g[0]));
                float F = siga(fmaf(wxg[1], x1, dif[3] + b0g[1]));
                float G = tanha(fmaf(wxg[2], x1, dgo[1] + b0g[2]));
                float O = siga(fmaf(wxg[3], x1, dgo[3] + b0g[3]));
                c0[e+1] = fmaf(F, c0[e+1], I * G);
                wr_h(h0w_hi, h0w_lo, s0 + 1, u, O * tanha(c0[e+1]));
            }
        }
        __syncthreads();

        // ================= layer 1 =================
#pragma unroll
        for (int nt = 0; nt < NT; nt++) {
            float dif[4] = {0,0,0,0}, dgo[4] = {0,0,0,0};
#pragma unroll
            for (int kt = 0; kt < 4; kt++) {
                const u32 ro = (u32)((nt * 8 + g4) * H_STRIDE + kt * 32 + t4 * 4);
                u32 p0h = *(const u32*)(h0w_hi + ro);
                u32 p1h = *(const u32*)(h0w_hi + ro + 16);
                u32 p0l = *(const u32*)(h0w_lo + ro);
                u32 p1l = *(const u32*)(h0w_lo + ro + 16);
                u32 q0h = *(const u32*)(h1r_hi + ro);
                u32 q1h = *(const u32*)(h1r_hi + ro + 16);
                u32 q0l = *(const u32*)(h1r_lo + ro);
                u32 q1l = *(const u32*)(h1r_lo + ro + 16);
                mmaf16(dif, &aW1[kt*8+0], p0h, p1h);
                mmaf16(dif, &aW1[kt*8+0], p0l, p1l);
                mmaf16(dif, &aW2[kt*8+0], q0h, q1h);
                mmaf16(dif, &aW2[kt*8+0], q0l, q1l);
                mmaf16(dgo, &aW1[kt*8+4], p0h, p1h);
                mmaf16(dgo, &aW1[kt*8+4], p0l, p1l);
                mmaf16(dgo, &aW2[kt*8+4], q0h, q1h);
                mmaf16(dgo, &aW2[kt*8+4], q0l, q1l);
            }
            const int s0 = nt * 8 + 2 * t4;
            const int e = nt * 2;
            {
                float I = siga(dif[0] + b1g[0]);
                float F = siga(dif[2] + b1g[1]);
                float G = tanha(dgo[0] + b1g[2]);
                float O = siga(dgo[2] + b1g[3]);
                c1[e] = fmaf(F, c1[e], I * G);
                wr_h(h1w_hi, h1w_lo, s0, u, O * tanha(c1[e]));
            }
            {
                float I = siga(dif[1] + b1g[0]);
                float F = siga(dif[3] + b1g[1]);
                float G = tanha(dgo[1] + b1g[2]);
                float O = siga(dgo[3] + b1g[3]);
                c1[e+1] = fmaf(F, c1[e+1], I * G);
                wr_h(h1w_hi, h1w_lo, s0 + 1, u, O * tanha(c1[e+1]));
            }
        }
        __syncthreads();
    }

    // final h1 lives in ping 0 (tt=63: p=1, wrote p^1=0)
    const __half* fh_hi = (const __half*)(smem + HOFF(1, 0, 0));
    const __half* fh_lo = (const __half*)(smem + HOFF(1, 0, 1));

    // ---- hT output (coalesced) ----
    for (int i = tid; i < cnt * 64; i += NTHREADS) {
        int s = i >> 6, k = i & 63;
        float h = __half2float(fh_hi[s * 72 + k]) + __half2float(fh_lo[s * 72 + k]);
        out[(size_t)(start + s) * 64 + k] = h;
    }
    // ---- FC head ----
    if (tid < cnt) {
        const int s = tid;
        const float xl = sx[s * 65 + 63];
        float acc = fc2_b[0];
#pragma unroll 1
        for (int uu = 0; uu < 16; uu++) {
            float a1 = fc1_b[uu];
#pragma unroll 4
            for (int k = 0; k < 64; k++) {
                float h = __half2float(fh_hi[s * 72 + k]) + __half2float(fh_lo[s * 72 + k]);
                a1 = fmaf(fc1_w[uu * 65 + k], h, a1);
            }
            a1 = fmaf(fc1_w[uu * 65 + 64], xl, a1);
            acc = fmaf(fc2_w[uu], fmaxf(a1, 0.0f), acc);
        }
        out[(size_t)BN * 64 + start + s] = acc;
    }
}

extern "C" void kernel_launch(void* const* d_in, const int* in_sizes, int n_in,
                              void* d_out, int out_size) {
    (void)in_sizes; (void)n_in; (void)out_size;
    cudaFuncSetAttribute(lstm_mma, cudaFuncAttributeMaxDynamicSharedMemorySize, SMEM_BYTES);
    lstm_mma<<<NBLOCKS, NTHREADS, SMEM_BYTES>>>(
        (const float*)d_in[0],  (const float*)d_in[1],  (const float*)d_in[2],
        (const float*)d_in[3],  (const float*)d_in[4],  (const float*)d_in[5],
        (const float*)d_in[6],  (const float*)d_in[7],  (const float*)d_in[8],
        (const float*)d_in[9],  (const float*)d_in[10], (const float*)d_in[11],
        (const float*)d_in[12], (float*)d_out);
}

// round 8
// speedup vs baseline: 7.2909x; 1.5407x over previous
#include <cuda_runtime.h>
#include <cuda_fp16.h>
#include <cstdint>

#define NTHREADS 512
#define NBLOCKS  148
#define BN       9600
#define SEQ_CAP  72
#define NT       9

typedef unsigned int u32;

#define H_STRIDE 144
#define HB_SZ    (SEQ_CAP * H_STRIDE)          // 10368
#define OFF_H0(p)  ((p) * HB_SZ)
#define OFF_H1(p)  ((2 + (p)) * HB_SZ)
#define OFF_H1LO   (4 * HB_SZ)
#define OFF_X      (5 * HB_SZ)                 // 51840
#define SMEM_BYTES (OFF_X + SEQ_CAP * 65 * 4)  // 70560

__device__ __forceinline__ void mmaf16(float* d, const u32* a, u32 b0, u32 b1) {
    asm volatile(
        "mma.sync.aligned.m16n8k16.row.col.f32.f16.f16.f32 "
        "{%0,%1,%2,%3}, {%4,%5,%6,%7}, {%8,%9}, {%0,%1,%2,%3};"
        : "+f"(d[0]), "+f"(d[1]), "+f"(d[2]), "+f"(d[3])
        : "r"(a[0]), "r"(a[1]), "r"(a[2]), "r"(a[3]), "r"(b0), "r"(b1));
}
__device__ __forceinline__ u32 h2u(float f0, float f1) {
    __half2 h = __floats2half2_rn(f0, f1);
    return *(u32*)&h;
}
__device__ __forceinline__ float tanha(float x) {
    float r;
    asm("tanh.approx.f32 %0, %1;" : "=f"(r) : "f"(x));
    return r;
}
__device__ __forceinline__ float siga(float x) { return fmaf(0.5f, tanha(0.5f * x), 0.5f); }

__global__ void __launch_bounds__(NTHREADS, 1)
lstm_mma(const float* __restrict__ x,
         const float* __restrict__ Wih0, const float* __restrict__ Whh0,
         const float* __restrict__ bih0, const float* __restrict__ bhh0,
         const float* __restrict__ Wih1, const float* __restrict__ Whh1,
         const float* __restrict__ bih1, const float* __restrict__ bhh1,
         const float* __restrict__ fc1_w, const float* __restrict__ fc1_b,
         const float* __restrict__ fc2_w, const float* __restrict__ fc2_b,
         float* __restrict__ out)
{
    extern __shared__ char smem[];
    float* sx = (float*)(smem + OFF_X);

    const int tid  = threadIdx.x;
    const int wid  = tid >> 5;
    const int lane = tid & 31;
    const int g4   = lane >> 2;
    const int t4   = lane & 3;
    const bool isA = (wid < 8);             // layer-0 group
    const int wl   = isA ? wid : (wid - 8); // warp index within group
    const int u    = wl * 8 + g4;           // hidden unit owned
    const int b    = blockIdx.x;
    const int cnt  = 64 + (b < 128 ? 1 : 0);
    const int start = b * 64 + (b < 128 ? b : 128);

    // ---- W fp16 A-fragments (permuted rows; group-specific) ----
    u32 aWa[32];            // A-group: Whh0
    u32 aWb1[32], aWb2[32]; // B-group: Wih1, Whh1
#pragma unroll
    for (int kt = 0; kt < 4; kt++)
#pragma unroll
        for (int T = 0; T < 2; T++) {
            const int r0 = ((2 * T) * 64 + u) * 64;
            const int r1 = ((2 * T + 1) * 64 + u) * 64;
            const int k0 = kt * 16 + 2 * t4;
            const int i = kt * 8 + T * 4;
            if (isA) {
                aWa[i+0] = h2u(Whh0[r0+k0],   Whh0[r0+k0+1]);
                aWa[i+1] = h2u(Whh0[r1+k0],   Whh0[r1+k0+1]);
                aWa[i+2] = h2u(Whh0[r0+k0+8], Whh0[r0+k0+9]);
                aWa[i+3] = h2u(Whh0[r1+k0+8], Whh0[r1+k0+9]);
            } else {
                aWb1[i+0] = h2u(Wih1[r0+k0],   Wih1[r0+k0+1]);
                aWb1[i+1] = h2u(Wih1[r1+k0],   Wih1[r1+k0+1]);
                aWb1[i+2] = h2u(Wih1[r0+k0+8], Wih1[r0+k0+9]);
                aWb1[i+3] = h2u(Wih1[r1+k0+8], Wih1[r1+k0+9]);
                aWb2[i+0] = h2u(Whh1[r0+k0],   Whh1[r0+k0+1]);
                aWb2[i+1] = h2u(Whh1[r1+k0],   Whh1[r1+k0+1]);
                aWb2[i+2] = h2u(Whh1[r0+k0+8], Whh1[r0+k0+9]);
                aWb2[i+3] = h2u(Whh1[r1+k0+8], Whh1[r1+k0+9]);
            }
        }

    float wxg[4], bg[4];
#pragma unroll
    for (int g = 0; g < 4; g++) {
        int row = g * 64 + u;
        if (isA) {
            wxg[g] = Wih0[row];
            bg[g]  = bih0[row] + bhh0[row];
        } else {
            wxg[g] = 0.0f;
            bg[g]  = bih1[row] + bhh1[row];
        }
    }

    // ---- zero h buffers; stage x ----
    for (int i = tid; i < (4 * HB_SZ) / 4; i += NTHREADS) ((u32*)smem)[i] = 0u;
    for (int i = tid; i < SEQ_CAP * 64; i += NTHREADS) {
        int s = i >> 6, t = i & 63;
        sx[s * 65 + t] = (s < cnt) ? x[(size_t)(start + s) * 64 + t] : 0.0f;
    }
    __syncthreads();

    float cst[2 * NT];
#pragma unroll
    for (int i = 0; i < 2 * NT; i++) cst[i] = 0.0f;

    for (int k = 0; k <= 64; k++) {
        if (isA) {
            if (k < 64) {
                // ---- layer 0, step k: read H0[k&1], write H0[(k+1)&1] ----
                const char* hr = smem + OFF_H0(k & 1);
                char* hw = smem + OFF_H0((k + 1) & 1);
#pragma unroll
                for (int nt = 0; nt < NT; nt++) {
                    float dif[4] = {0,0,0,0}, dgo[4] = {0,0,0,0};
#pragma unroll
                    for (int kt = 0; kt < 4; kt++) {
                        const u32 ro = (u32)((nt * 8 + g4) * H_STRIDE + kt * 32 + t4 * 4);
                        u32 b0h = *(const u32*)(hr + ro);
                        u32 b1h = *(const u32*)(hr + ro + 16);
                        mmaf16(dif, &aWa[kt*8+0], b0h, b1h);
                        mmaf16(dgo, &aWa[kt*8+4], b0h, b1h);
                    }
                    const int s0 = nt * 8 + 2 * t4;
                    const float x0 = sx[s0 * 65 + k];
                    const float x1 = sx[s0 * 65 + 65 + k];
                    const int e = nt * 2;
#pragma unroll
                    for (int q = 0; q < 2; q++) {
                        const float xq = q ? x1 : x0;
                        float I = siga(fmaf(wxg[0], xq, dif[0+q] + bg[0]));
                        float F = siga(fmaf(wxg[1], xq, dif[2+q] + bg[1]));
                        float G = tanha(fmaf(wxg[2], xq, dgo[0+q] + bg[2]));
                        float O = siga(fmaf(wxg[3], xq, dgo[2+q] + bg[3]));
                        cst[e+q] = fmaf(F, cst[e+q], I * G);
                        float h0 = O * tanha(cst[e+q]);
                        *(__half*)(hw + (u32)((s0 + q) * H_STRIDE + u * 2)) = __float2half_rn(h0);
                    }
                }
            }
        } else {
            if (k >= 1) {
                // ---- layer 1, step k-1: read H0[k&1], H1[(k-1)&1], write H1[k&1] ----
                const char* h0r = smem + OFF_H0(k & 1);
                const char* h1r = smem + OFF_H1((k - 1) & 1);
                char* h1w = smem + OFF_H1(k & 1);
                char* h1lo = smem + OFF_H1LO;
                const bool last = (k == 64);
#pragma unroll
                for (int nt = 0; nt < NT; nt++) {
                    float dif[4] = {0,0,0,0}, dgo[4] = {0,0,0,0};
#pragma unroll
                    for (int kt = 0; kt < 4; kt++) {
                        const u32 ro = (u32)((nt * 8 + g4) * H_STRIDE + kt * 32 + t4 * 4);
                        u32 p0 = *(const u32*)(h0r + ro);
                        u32 p1 = *(const u32*)(h0r + ro + 16);
                        u32 q0 = *(const u32*)(h1r + ro);
                        u32 q1 = *(const u32*)(h1r + ro + 16);
                        mmaf16(dif, &aWb1[kt*8+0], p0, p1);
                        mmaf16(dgo, &aWb1[kt*8+4], p0, p1);
                        mmaf16(dif, &aWb2[kt*8+0], q0, q1);
                        mmaf16(dgo, &aWb2[kt*8+4], q0, q1);
                    }
                    const int s0 = nt * 8 + 2 * t4;
                    const int e = nt * 2;
#pragma unroll
                    for (int q = 0; q < 2; q++) {
                        float I = siga(dif[0+q] + bg[0]);
                        float F = siga(dif[2+q] + bg[1]);
                        float G = tanha(dgo[0+q] + bg[2]);
                        float O = siga(dgo[2+q] + bg[3]);
                        cst[e+q] = fmaf(F, cst[e+q], I * G);
                        float h1 = O * tanha(cst[e+q]);
                        u32 off = (u32)((s0 + q) * H_STRIDE + u * 2);
                        __half hh = __float2half_rn(h1);
                        *(__half*)(h1w + off) = hh;
                        if (last)
                            *(__half*)(h1lo + off) = __float2half_rn(h1 - __half2float(hh));
                    }
                }
            }
        }
        __syncthreads();
    }

    // final h1 = H1[0] (k=64 writes slot 0) + lo residual
    const __half* fh = (const __half*)(smem + OFF_H1(0));
    const __half* fl = (const __half*)(smem + OFF_H1LO);

    for (int i = tid; i < cnt * 64; i += NTHREADS) {
        int s = i >> 6, kk = i & 63;
        out[(size_t)(start + s) * 64 + kk] =
            __half2float(fh[s * 72 + kk]) + __half2float(fl[s * 72 + kk]);
    }
    if (tid < cnt) {
        const int s = tid;
        const float xl = sx[s * 65 + 63];
        float acc = fc2_b[0];
#pragma unroll 1
        for (int uu = 0; uu < 16; uu++) {
            float a1 = fc1_b[uu];
#pragma unroll 4
            for (int kk = 0; kk < 64; kk++) {
                float h = __half2float(fh[s * 72 + kk]) + __half2float(fl[s * 72 + kk]);
                a1 = fmaf(fc1_w[uu * 65 + kk], h, a1);
            }
            a1 = fmaf(fc1_w[uu * 65 + 64], xl, a1);
            acc = fmaf(fc2_w[uu], fmaxf(a1, 0.0f), acc);
        }
        out[(size_t)BN * 64 + start + s] = acc;
    }
}

extern "C" void kernel_launch(void* const* d_in, const int* in_sizes, int n_in,
                              void* d_out, int out_size) {
    (void)in_sizes; (void)n_in; (void)out_size;
    cudaFuncSetAttribute(lstm_mma, cudaFuncAttributeMaxDynamicSharedMemorySize, SMEM_BYTES);
    lstm_mma<<<NBLOCKS, NTHREADS, SMEM_BYTES>>>(
        (const float*)d_in[0],  (const float*)d_in[1],  (const float*)d_in[2],
        (const float*)d_in[3],  (const float*)d_in[4],  (const float*)d_in[5],
        (const float*)d_in[6],  (const float*)d_in[7],  (const float*)d_in[8],
        (const float*)d_in[9],  (const float*)d_in[10], (const float*)d_in[11],
        (const float*)d_in[12], (float*)d_out);
}